// round 14
// baseline (speedup 1.0000x reference)
#include <cuda_runtime.h>
#include <mma.h>
using namespace nvcuda;

#define Nn   100000
#define Ee   3200000
#define HID  64
#define INF  500
#define CLS  40
#define KK   10

#define GS_BLOCKS 592   // 4 per SM x 148 SMs: guaranteed co-resident (grid barrier safety)
#define SCAN_BLOCKS ((Nn + 1023)/1024)   // 98 blocks of 1024: 1/SM, co-resident

typedef unsigned long long ull;

// ---------------- host-side stream/event resources (created pre-main, outside capture) ----------------
struct HostRes {
    cudaStream_t s2;
    cudaEvent_t evFork, evJoin;
    HostRes(){
        cudaStreamCreateWithFlags(&s2, cudaStreamNonBlocking);
        cudaEventCreateWithFlags(&evFork, cudaEventDisableTiming);
        cudaEventCreateWithFlags(&evJoin, cudaEventDisableTiming);
    }
};
static HostRes g_res;

// ---------------- device scratch (static; zero-initialized at load) ----------------
__device__ float g_U[KK+1][Nn*HID];         // raw (unnormalized) basis vectors U_0..U_K
__device__ ull   g_edge[Ee];                // packed {src, w}
__device__ int   g_rank[Ee];
__device__ int   g_rowptr[Nn+1];
__device__ int   g_cnt[Nn];
__device__ int   g_bsum[SCAN_BLOCKS];
__device__ float g_dots[(KK+1)*192];        // per-iter: d1[64] | d2[64] | d12[64]
__device__ float g_ss  [(KK+1)*64];         // per-iter column sum-of-squares
__device__ float g_inv [(KK+2)*HID];        // slot(i+1) = inv_i ; slot 0 (= inv_{-1}) stays zero
__device__ unsigned g_sync[KK+1];           // per-iter grid-barrier counters (k_gs)
__device__ unsigned g_sync2;                // grid-barrier counter (k_scan_fused)

// ---------------- init ----------------
__global__ void k_zero(){
    int i = blockIdx.x*blockDim.x + threadIdx.x;
    if (i < Nn) g_cnt[i] = 0;
    if (i < (KK+1)*192) g_dots[i] = 0.f;
    if (i < (KK+1)*64)  g_ss[i]   = 0.f;
    if (i < KK+1)       g_sync[i] = 0u;
    if (i == 0)         g_sync2   = 0u;
}

// ---------------- CSR build ----------------
__global__ void k_count(const int* __restrict__ dst){
    int e = blockIdx.x*blockDim.x + threadIdx.x;
    if (e < Ee) g_rank[e] = atomicAdd(&g_cnt[dst[e]], 1);
}

// fused scan (replaces scan1+scan2+scan3) with grid barrier; grid MUST be SCAN_BLOCKS
__global__ void __launch_bounds__(1024, 1) k_scan_fused(){
    __shared__ int s[1024];
    __shared__ int sb[SCAN_BLOCKS];
    __shared__ int offs;
    int t = threadIdx.x;
    int base = blockIdx.x*1024;
    int v = (base + t < Nn) ? g_cnt[base + t] : 0;
    s[t] = v; __syncthreads();
    for (int d = 1; d < 1024; d <<= 1){
        int add = (t >= d) ? s[t-d] : 0;
        __syncthreads();
        s[t] += add;
        __syncthreads();
    }
    if (t == 1023){
        g_bsum[blockIdx.x] = s[1023];
        __threadfence();                    // release bsum before arrive
    }
    __syncthreads();
    if (t == 0){
        atomicAdd(&g_sync2, 1u);
        volatile unsigned* sy = (volatile unsigned*)&g_sync2;
        while (*sy < (unsigned)gridDim.x) __nanosleep(32);
        __threadfence();                    // acquire
    }
    __syncthreads();
    if (t < SCAN_BLOCKS) sb[t] = g_bsum[t];
    __syncthreads();
    if (t == 0){
        int acc = 0;
        for (int b = 0; b < blockIdx.x; b++) acc += sb[b];
        offs = acc;
    }
    __syncthreads();
    if (base + t < Nn) g_rowptr[base + t + 1] = s[t] + offs;
    if (blockIdx.x == 0 && t == 0) g_rowptr[0] = 0;
}

__global__ void k_scatter(const int* __restrict__ src, const int* __restrict__ dst,
                          const float* __restrict__ w){
    int e = blockIdx.x*blockDim.x + threadIdx.x;
    if (e >= Ee) return;
    int d   = dst[e];
    int pos = g_rowptr[d] + g_rank[e];
    ull pk = (unsigned int)src[e] | ((ull)__float_as_uint(w[e]) << 32);
    g_edge[pos] = pk;
}

// ---------------- fc1 (tf32 wmma): U0 = relu(feat@W1 + b1) + 1e-5*noise ; col sumsq -> g_ss[0] ----
// 128 rows x 64 cols per block, 8 warps, each warp 16 rows x 64 cols (4 m16n16k8 accumulators).
#define FBM 128
__global__ void __launch_bounds__(256) k_fc1(const float* __restrict__ A, const float* __restrict__ W,
                      const float* __restrict__ b1, const float* __restrict__ noise){
    __shared__ float As[FBM][8];
    __shared__ float Bs[8][64];
    __shared__ float Cs[FBM][64];
    __shared__ float scol[HID];
    int tid = threadIdx.x;
    int w   = tid >> 5;
    int rowbase = blockIdx.x * FBM;
    if (tid < HID) scol[tid] = 0.f;

    wmma::fragment<wmma::accumulator, 16,16,8, float> acc[4];
    #pragma unroll
    for (int n = 0; n < 4; n++) wmma::fill_fragment(acc[n], 0.f);

    // A-load mapping: 128 rows x 8 k = 256 float4 (one per thread)
    int arow  = tid >> 1, ahalf = tid & 1;
    int growA = rowbase + arow;
    bool avalid = (growA < Nn);
    const float* aptr = A + (avalid ? growA : 0)*INF;
    // B-load mapping (tid < 128): 8 k-rows x 64 = 128 float4
    int bk = tid >> 4, bc = (tid & 15)*4;

    for (int k0 = 0; k0 < 504; k0 += 8){
        int kk = k0 + ahalf*4;
        float4 va = make_float4(0.f,0.f,0.f,0.f);
        if (avalid && kk < INF) va = *(const float4*)(aptr + kk);  // INF=500: kk=496 full, kk=500 skipped
        *(float4*)&As[arow][ahalf*4] = va;
        if (tid < 128){
            float4 vb = make_float4(0.f,0.f,0.f,0.f);
            int krow = k0 + bk;
            if (krow < INF) vb = *(const float4*)(W + krow*HID + bc);
            *(float4*)&Bs[bk][bc] = vb;
        }
        __syncthreads();
        wmma::fragment<wmma::matrix_a, 16,16,8, wmma::precision::tf32, wmma::row_major> af;
        wmma::load_matrix_sync(af, &As[w*16][0], 8);
        #pragma unroll
        for (int i = 0; i < af.num_elements; i++) af.x[i] = wmma::__float_to_tf32(af.x[i]);
        #pragma unroll
        for (int n = 0; n < 4; n++){
            wmma::fragment<wmma::matrix_b, 16,16,8, wmma::precision::tf32, wmma::row_major> bf;
            wmma::load_matrix_sync(bf, &Bs[0][n*16], 64);
            #pragma unroll
            for (int i = 0; i < bf.num_elements; i++) bf.x[i] = wmma::__float_to_tf32(bf.x[i]);
            wmma::mma_sync(acc[n], af, bf, acc[n]);
        }
        __syncthreads();
    }

    #pragma unroll
    for (int n = 0; n < 4; n++)
        wmma::store_matrix_sync(&Cs[w*16][n*16], acc[n], 64, wmma::mem_row_major);
    __syncthreads();

    // epilogue: bias + relu + noise + column sumsq (same math as scalar fc1)
    int c4 = (tid & 15) * 4;     // constant per thread across its rows
    float4 bj = *(const float4*)(b1 + c4);
    float css[4] = {0.f,0.f,0.f,0.f};
    #pragma unroll
    for (int i = 0; i < 8; i++){
        int idx = tid + i*256;           // 0..2047 float4 slots
        int row = idx >> 4;
        int growe = rowbase + row;
        if (growe < Nn){
            float4 c  = *(const float4*)&Cs[row][c4];
            float4 nz = *(const float4*)(noise + growe*HID + c4);
            float4 v;
            v.x = fmaf(1e-5f, nz.x, fmaxf(c.x + bj.x, 0.f));
            v.y = fmaf(1e-5f, nz.y, fmaxf(c.y + bj.y, 0.f));
            v.z = fmaf(1e-5f, nz.z, fmaxf(c.z + bj.z, 0.f));
            v.w = fmaf(1e-5f, nz.w, fmaxf(c.w + bj.w, 0.f));
            css[0] = fmaf(v.x, v.x, css[0]);
            css[1] = fmaf(v.y, v.y, css[1]);
            css[2] = fmaf(v.z, v.z, css[2]);
            css[3] = fmaf(v.w, v.w, css[3]);
            *(float4*)(g_U[0] + growe*HID + c4) = v;
        }
    }
    atomicAdd(&scol[c4  ], css[0]); atomicAdd(&scol[c4+1], css[1]);
    atomicAdd(&scol[c4+2], css[2]); atomicAdd(&scol[c4+3], css[3]);
    __syncthreads();
    if (tid < HID) atomicAdd(&g_ss[tid], scol[tid]);
}

// ---------------- SpMM: R = inv_{i-1} .* (A @ U1), one warp per dst row (FROZEN R8 body) ----------------
__global__ void k_spmm(int u1Idx, int rIdx, int iter){
    const float* __restrict__ U = g_U[u1Idx];
    float* __restrict__ R = g_U[rIdx];
    __shared__ float inv_s[64];
    int t = threadIdx.x;
    if (t < 64){
        float ss = g_ss[(iter-1)*64 + t];
        float iv = 1.f / fmaxf(sqrtf(ss), 1e-8f);
        inv_s[t] = iv;
        if (blockIdx.x == 0) g_inv[iter*64 + t] = iv;
    }
    __syncthreads();
    int w    = (blockIdx.x*blockDim.x + t) >> 5;
    int lane = t & 31;
    if (w >= Nn) return;
    int e   = g_rowptr[w];
    int end = g_rowptr[w+1];
    float a0 = 0.f, a1 = 0.f;
    for (; e + 3 < end; e += 4){
        ull p0 = g_edge[e];
        ull p1 = g_edge[e+1];
        ull p2 = g_edge[e+2];
        ull p3 = g_edge[e+3];
        int   s0 = (int)(p0 & 0xffffffffu); float w0 = __uint_as_float((unsigned int)(p0 >> 32));
        int   s1 = (int)(p1 & 0xffffffffu); float w1 = __uint_as_float((unsigned int)(p1 >> 32));
        int   s2 = (int)(p2 & 0xffffffffu); float w2 = __uint_as_float((unsigned int)(p2 >> 32));
        int   s3 = (int)(p3 & 0xffffffffu); float w3 = __uint_as_float((unsigned int)(p3 >> 32));
        float2 v0 = *(const float2*)(U + (s0 << 6) + (lane << 1));
        float2 v1 = *(const float2*)(U + (s1 << 6) + (lane << 1));
        float2 v2 = *(const float2*)(U + (s2 << 6) + (lane << 1));
        float2 v3 = *(const float2*)(U + (s3 << 6) + (lane << 1));
        a0 = fmaf(w0, v0.x, a0); a1 = fmaf(w0, v0.y, a1);
        a0 = fmaf(w1, v1.x, a0); a1 = fmaf(w1, v1.y, a1);
        a0 = fmaf(w2, v2.x, a0); a1 = fmaf(w2, v2.y, a1);
        a0 = fmaf(w3, v3.x, a0); a1 = fmaf(w3, v3.y, a1);
    }
    for (; e < end; e++){
        ull p0 = g_edge[e];
        int   s0 = (int)(p0 & 0xffffffffu);
        float w0 = __uint_as_float((unsigned int)(p0 >> 32));
        float2 v0 = *(const float2*)(U + (s0 << 6) + (lane << 1));
        a0 = fmaf(w0, v0.x, a0); a1 = fmaf(w0, v0.y, a1);
    }
    float2 o;
    o.x = a0 * inv_s[lane*2];
    o.y = a1 * inv_s[lane*2 + 1];
    *(float2*)(R + (w << 6) + (lane << 1)) = o;
}

// ---------------- fused Gram-Schmidt step: dots -> grid barrier -> subtract + sumsq (FROZEN R8) ----
// Grid MUST be GS_BLOCKS (all co-resident) for the barrier to be deadlock-free.
__global__ void __launch_bounds__(256, 4) k_gs(int rIdx, int u1Idx, int u2Idx, int iter, int hasU2){
    float4* __restrict__ R        = (float4*)g_U[rIdx];
    const float4* __restrict__ U1 = (const float4*)g_U[u1Idx];
    const float4* __restrict__ U2 = (const float4*)g_U[u2Idx];
    __shared__ float s[192];
    int t = threadIdx.x;
    int c4 = (t & 15) * 4;
    int tid = blockIdx.x*blockDim.x + t;
    int stride = gridDim.x*blockDim.x;

    // ---- phase 1: column dot products ----
    float4 d1 = make_float4(0,0,0,0), d2 = d1, d3 = d1;
    if (hasU2){
        for (int i = tid; i < Nn*16; i += stride){
            float4 r = R[i], u1 = U1[i], u2 = U2[i];
            d1.x = fmaf(r.x,  u1.x, d1.x); d1.y = fmaf(r.y,  u1.y, d1.y);
            d1.z = fmaf(r.z,  u1.z, d1.z); d1.w = fmaf(r.w,  u1.w, d1.w);
            d2.x = fmaf(r.x,  u2.x, d2.x); d2.y = fmaf(r.y,  u2.y, d2.y);
            d2.z = fmaf(r.z,  u2.z, d2.z); d2.w = fmaf(r.w,  u2.w, d2.w);
            d3.x = fmaf(u1.x, u2.x, d3.x); d3.y = fmaf(u1.y, u2.y, d3.y);
            d3.z = fmaf(u1.z, u2.z, d3.z); d3.w = fmaf(u1.w, u2.w, d3.w);
        }
    } else {
        for (int i = tid; i < Nn*16; i += stride){
            float4 r = R[i], u1 = U1[i];
            d1.x = fmaf(r.x,  u1.x, d1.x); d1.y = fmaf(r.y,  u1.y, d1.y);
            d1.z = fmaf(r.z,  u1.z, d1.z); d1.w = fmaf(r.w,  u1.w, d1.w);
        }
    }
    if (t < 192) s[t] = 0.f;
    __syncthreads();
    atomicAdd(&s[      c4  ], d1.x); atomicAdd(&s[      c4+1], d1.y);
    atomicAdd(&s[      c4+2], d1.z); atomicAdd(&s[      c4+3], d1.w);
    if (hasU2){
        atomicAdd(&s[ 64 + c4  ], d2.x); atomicAdd(&s[ 64 + c4+1], d2.y);
        atomicAdd(&s[ 64 + c4+2], d2.z); atomicAdd(&s[ 64 + c4+3], d2.w);
        atomicAdd(&s[128 + c4  ], d3.x); atomicAdd(&s[128 + c4+1], d3.y);
        atomicAdd(&s[128 + c4+2], d3.z); atomicAdd(&s[128 + c4+3], d3.w);
    }
    __syncthreads();
    int nd = hasU2 ? 192 : 64;
    if (t < nd){
        atomicAdd(&g_dots[iter*192 + t], s[t]);
        __threadfence();        // release: dots visible before counter bump
    }
    __syncthreads();

    // ---- grid barrier ----
    if (t == 0){
        atomicAdd(&g_sync[iter], 1u);
        volatile unsigned* sy = (volatile unsigned*)&g_sync[iter];
        while (*sy < (unsigned)gridDim.x) __nanosleep(64);
        __threadfence();        // acquire
    }
    __syncthreads();

    // ---- phase 2: coefficients (MGS-exact), subtract, sumsq ----
    __shared__ float c1s[64], c2s[64], sss[64];
    if (t < 64){
        double inv1 = (double)g_inv[iter*64 + t];       // inv_{i-1}
        double inv2 = (double)g_inv[(iter-1)*64 + t];   // inv_{i-2} (slot 0 zeros at i==1)
        double d1v  = (double)__ldcg(&g_dots[iter*192 + t]);
        double d2v  = (double)__ldcg(&g_dots[iter*192 + 64 + t]);
        double d12  = (double)__ldcg(&g_dots[iter*192 + 128 + t]);
        double c1   = d1v*inv1*inv1;
        c1s[t] = (float)c1;                              // coeff on U1
        c2s[t] = (float)(inv2*inv2*(d2v - c1*d12));      // coeff on U2
        sss[t] = 0.f;
    }
    __syncthreads();
    float4 c1v = *(const float4*)&c1s[c4];
    float4 c2v = *(const float4*)&c2s[c4];
    float4 ss  = make_float4(0,0,0,0);
    if (hasU2){
        for (int i = tid; i < Nn*16; i += stride){
            float4 r = R[i], u1 = U1[i], u2 = U2[i];
            float4 w;
            w.x = r.x - c1v.x*u1.x - c2v.x*u2.x;
            w.y = r.y - c1v.y*u1.y - c2v.y*u2.y;
            w.z = r.z - c1v.z*u1.z - c2v.z*u2.z;
            w.w = r.w - c1v.w*u1.w - c2v.w*u2.w;
            ss.x = fmaf(w.x, w.x, ss.x); ss.y = fmaf(w.y, w.y, ss.y);
            ss.z = fmaf(w.z, w.z, ss.z); ss.w = fmaf(w.w, w.w, ss.w);
            R[i] = w;
        }
    } else {
        for (int i = tid; i < Nn*16; i += stride){
            float4 r = R[i], u1 = U1[i];
            float4 w;
            w.x = r.x - c1v.x*u1.x;
            w.y = r.y - c1v.y*u1.y;
            w.z = r.z - c1v.z*u1.z;
            w.w = r.w - c1v.w*u1.w;
            ss.x = fmaf(w.x, w.x, ss.x); ss.y = fmaf(w.y, w.y, ss.y);
            ss.z = fmaf(w.z, w.z, ss.z); ss.w = fmaf(w.w, w.w, ss.w);
            R[i] = w;
        }
    }
    atomicAdd(&sss[c4  ], ss.x); atomicAdd(&sss[c4+1], ss.y);
    atomicAdd(&sss[c4+2], ss.z); atomicAdd(&sss[c4+3], ss.w);
    __syncthreads();
    if (t < 64) atomicAdd(&g_ss[iter*64 + t], sss[t]);
}

// ---------------- final: out = (sum_i alpha_i*inv_i .* U_i) @ W2 + b2 ----------------
__global__ void __launch_bounds__(256) k_out(const float* __restrict__ W2, const float* __restrict__ b2,
                      const float* __restrict__ alpha, float* __restrict__ out){
    __shared__ float Ts[128][65];
    __shared__ float Bs[HID][CLS + 1];
    __shared__ float ck[KK+1][64];
    int tid = threadIdx.x;
    int rowbase = blockIdx.x * 128;
    if (tid < 64){
        #pragma unroll
        for (int i = 0; i < KK; i++)
            ck[i][tid] = alpha[tid*(KK+1) + i] * g_inv[(i+1)*64 + tid];
        float ssK  = g_ss[KK*64 + tid];
        float invK = 1.f / fmaxf(sqrtf(ssK), 1e-8f);
        ck[KK][tid] = alpha[tid*(KK+1) + KK] * invK;
    }
    for (int f = tid; f < HID*CLS; f += 256) Bs[f / CLS][f % CLS] = W2[f];
    __syncthreads();
    for (int f = tid; f < 128*64; f += 256){
        int r = f >> 6, col = f & 63;
        int grow = rowbase + r;
        float v = 0.f;
        if (grow < Nn){
            int idx = grow*64 + col;
            #pragma unroll
            for (int i = 0; i <= KK; i++)
                v = fmaf(ck[i][col], g_U[i][idx], v);
        }
        Ts[r][col] = v;
    }
    __syncthreads();
    int tr = tid & 31;   // rows tr*4..tr*4+3
    int tc = tid >> 5;   // cols tc*5..tc*5+4
    float acc[4][5];
    #pragma unroll
    for (int i = 0; i < 4; i++)
        #pragma unroll
        for (int j = 0; j < 5; j++) acc[i][j] = 0.f;
    for (int k = 0; k < 64; k++){
        float a[4], bb[5];
        #pragma unroll
        for (int i = 0; i < 4; i++) a[i] = Ts[tr*4 + i][k];
        #pragma unroll
        for (int j = 0; j < 5; j++) bb[j] = Bs[k][tc*5 + j];
        #pragma unroll
        for (int i = 0; i < 4; i++)
            #pragma unroll
            for (int j = 0; j < 5; j++)
                acc[i][j] = fmaf(a[i], bb[j], acc[i][j]);
    }
    #pragma unroll
    for (int i = 0; i < 4; i++){
        int row = rowbase + tr*4 + i;
        if (row < Nn){
            #pragma unroll
            for (int j = 0; j < 5; j++){
                int col = tc*5 + j;
                out[row*CLS + col] = acc[i][j] + b2[col];
            }
        }
    }
}

// ---------------- launch ----------------
extern "C" void kernel_launch(void* const* d_in, const int* in_sizes, int n_in,
                              void* d_out, int out_size){
    (void)in_sizes; (void)n_in; (void)out_size;
    const float* feat  = (const float*)d_in[0];
    const float* noise = (const float*)d_in[1];
    const float* normA = (const float*)d_in[2];
    const float* W1    = (const float*)d_in[3];
    const float* b1    = (const float*)d_in[4];
    const float* W2    = (const float*)d_in[5];
    const float* b2    = (const float*)d_in[6];
    const float* alpha = (const float*)d_in[7];
    const int*   ei    = (const int*)  d_in[8];
    const int* src = ei;
    const int* dst = ei + Ee;
    float* out = (float*)d_out;

    const int TB = 256;
    cudaStream_t ms = 0;               // capture/main stream
    cudaStream_t s2 = g_res.s2;

    // zeroing must precede both branches
    k_zero<<<(Nn + TB - 1)/TB, TB, 0, ms>>>();
    cudaEventRecord(g_res.evFork, ms);
    cudaStreamWaitEvent(s2, g_res.evFork, 0);

    // --- branch A (s2): CSR build ---
    k_count     <<<(Ee + TB - 1)/TB, TB, 0, s2>>>(dst);
    k_scan_fused<<<SCAN_BLOCKS, 1024, 0, s2>>>();
    k_scatter   <<<(Ee + TB - 1)/TB, TB, 0, s2>>>(src, dst, normA);
    cudaEventRecord(g_res.evJoin, s2);

    // --- branch B (main): fc1 (tf32 wmma) ---
    k_fc1<<<(Nn + FBM - 1)/FBM, 256, 0, ms>>>(feat, W1, b1, noise);

    // join
    cudaStreamWaitEvent(ms, g_res.evJoin, 0);

    for (int i = 1; i <= KK; i++){
        int hasU2 = (i >= 2) ? 1 : 0;
        int u2 = (i >= 2) ? (i - 2) : 0;      // unused when hasU2=0
        k_spmm<<<(Nn*32 + TB - 1)/TB, TB, 0, ms>>>(i - 1, i, i);
        k_gs  <<<GS_BLOCKS, TB, 0, ms>>>(i, i - 1, u2, i, hasU2);
    }

    k_out<<<(Nn + 127)/128, 256, 0, ms>>>(W2, b2, alpha, out);
}

// round 15
// speedup vs baseline: 1.1128x; 1.1128x over previous
#include <cuda_runtime.h>
#include <mma.h>
using namespace nvcuda;

#define Nn   100000
#define Ee   3200000
#define HID  64
#define INF  500
#define CLS  40
#define KK   10

#define GS_BLOCKS 592   // 4 per SM x 148 SMs: guaranteed co-resident (grid barrier safety)
#define SCAN_BLOCKS ((Nn + 1023)/1024)   // 98 blocks of 1024: 1/SM, co-resident

typedef unsigned long long ull;

// ---------------- host-side stream/event resources (created pre-main, outside capture) ----------------
struct HostRes {
    cudaStream_t s2;
    cudaEvent_t evFork, evJoin;
    HostRes(){
        cudaStreamCreateWithFlags(&s2, cudaStreamNonBlocking);
        cudaEventCreateWithFlags(&evFork, cudaEventDisableTiming);
        cudaEventCreateWithFlags(&evJoin, cudaEventDisableTiming);
    }
};
static HostRes g_res;

// ---------------- device scratch (static; zero-initialized at load) ----------------
__device__ float g_U[KK+1][Nn*HID];         // raw (unnormalized) basis vectors U_0..U_K
__device__ ull   g_edge[Ee];                // packed {src, w}
__device__ int   g_rank[Ee];
__device__ int   g_rowptr[Nn+1];
__device__ int   g_cnt[Nn];
__device__ int   g_bsum[SCAN_BLOCKS];
__device__ float g_dots[(KK+1)*192];        // per-iter: d1[64] | d2[64] | d12[64]
__device__ float g_ss  [(KK+1)*64];         // per-iter column sum-of-squares
__device__ float g_inv [(KK+2)*HID];        // slot(i+1) = inv_i ; slot 0 (= inv_{-1}) stays zero
__device__ unsigned g_sync[KK+1];           // per-iter grid-barrier counters (k_gs)
__device__ unsigned g_sync2;                // grid-barrier counter (k_scan_fused)

// ---------------- init ----------------
__global__ void k_zero(){
    int i = blockIdx.x*blockDim.x + threadIdx.x;
    if (i < Nn) g_cnt[i] = 0;
    if (i < (KK+1)*192) g_dots[i] = 0.f;
    if (i < (KK+1)*64)  g_ss[i]   = 0.f;
    if (i < KK+1)       g_sync[i] = 0u;
    if (i == 0)         g_sync2   = 0u;
}

// ---------------- CSR build ----------------
__global__ void k_count(const int* __restrict__ dst){
    int e = blockIdx.x*blockDim.x + threadIdx.x;
    if (e < Ee) g_rank[e] = atomicAdd(&g_cnt[dst[e]], 1);
}

// fused scan (replaces scan1+scan2+scan3) with grid barrier; grid MUST be SCAN_BLOCKS
__global__ void __launch_bounds__(1024, 1) k_scan_fused(){
    __shared__ int s[1024];
    __shared__ int sb[SCAN_BLOCKS];
    __shared__ int offs;
    int t = threadIdx.x;
    int base = blockIdx.x*1024;
    int v = (base + t < Nn) ? g_cnt[base + t] : 0;
    s[t] = v; __syncthreads();
    for (int d = 1; d < 1024; d <<= 1){
        int add = (t >= d) ? s[t-d] : 0;
        __syncthreads();
        s[t] += add;
        __syncthreads();
    }
    if (t == 1023){
        g_bsum[blockIdx.x] = s[1023];
        __threadfence();                    // release bsum before arrive
    }
    __syncthreads();
    if (t == 0){
        atomicAdd(&g_sync2, 1u);
        volatile unsigned* sy = (volatile unsigned*)&g_sync2;
        while (*sy < (unsigned)gridDim.x) __nanosleep(32);
        __threadfence();                    // acquire
    }
    __syncthreads();
    if (t < SCAN_BLOCKS) sb[t] = g_bsum[t];
    __syncthreads();
    if (t == 0){
        int acc = 0;
        for (int b = 0; b < blockIdx.x; b++) acc += sb[b];
        offs = acc;
    }
    __syncthreads();
    if (base + t < Nn) g_rowptr[base + t + 1] = s[t] + offs;
    if (blockIdx.x == 0 && t == 0) g_rowptr[0] = 0;
}

__global__ void k_scatter(const int* __restrict__ src, const int* __restrict__ dst,
                          const float* __restrict__ w){
    int e = blockIdx.x*blockDim.x + threadIdx.x;
    if (e >= Ee) return;
    int d   = dst[e];
    int pos = g_rowptr[d] + g_rank[e];
    ull pk = (unsigned int)src[e] | ((ull)__float_as_uint(w[e]) << 32);
    g_edge[pos] = pk;
}

// ---------------- fc1 (tf32 wmma v2): U0 = relu(feat@W1 + b1) + 1e-5*noise ; col sumsq -> g_ss[0] ----
// 128 rows x 64 cols per block, 8 warps (warp w owns rows w*16..w*16+15, all 64 cols).
// K-chunk = 32 (16 chunks over padded K=512); smem union reuses input tiles for the C tile.
#define FBM 128
#define KC  32
#define NCH 16
#define LDA 36     // A smem row stride (floats): 16B-aligned rows, mult of 4
#define LDB 68     // B smem row stride
#define LDC 68
__global__ void __launch_bounds__(256) k_fc1(const float* __restrict__ A, const float* __restrict__ W,
                      const float* __restrict__ b1, const float* __restrict__ noise){
    __shared__ union SM {
        struct { float A[FBM][LDA]; float B[KC][LDB]; } in;   // 18432 + 8704 bytes
        float C[FBM][LDC];                                     // 34816 bytes
    } sm;
    __shared__ float scol[HID];
    int tid = threadIdx.x;
    int w   = tid >> 5;
    int rowbase = blockIdx.x * FBM;
    if (tid < HID) scol[tid] = 0.f;

    wmma::fragment<wmma::accumulator, 16,16,8, float> acc[4];
    #pragma unroll
    for (int n = 0; n < 4; n++) wmma::fill_fragment(acc[n], 0.f);

    // A-load mapping: 128 rows x 8 float4 = 1024 float4, 4 per thread
    int ar[4], aq[4]; bool avld[4]; const float4* aptr[4];
    #pragma unroll
    for (int s = 0; s < 4; s++){
        int f = tid + 256*s;
        ar[s] = f >> 3; aq[s] = f & 7;
        int grow = rowbase + ar[s];
        avld[s] = (grow < Nn);
        aptr[s] = (const float4*)(A + (avld[s] ? grow : 0)*INF) + aq[s];
    }
    // B-load mapping: 32 k-rows x 16 float4 = 512 float4, 2 per thread
    int bk[2], bc[2];
    #pragma unroll
    for (int s = 0; s < 2; s++){
        int f = tid + 256*s;
        bk[s] = f >> 4; bc[s] = (f & 15)*4;
    }

    for (int c = 0; c < NCH; c++){
        int k0 = c*KC;
        #pragma unroll
        for (int s = 0; s < 4; s++){
            int kcol = k0 + aq[s]*4;
            float4 v = make_float4(0.f,0.f,0.f,0.f);
            if (avld[s] && kcol < INF) v = aptr[s][k0 >> 2];   // INF divisible by 4: full or skip
            *(float4*)&sm.in.A[ar[s]][aq[s]*4] = v;
        }
        #pragma unroll
        for (int s = 0; s < 2; s++){
            int krow = k0 + bk[s];
            float4 v = make_float4(0.f,0.f,0.f,0.f);
            if (krow < INF) v = *(const float4*)(W + krow*HID + bc[s]);
            *(float4*)&sm.in.B[bk[s]][bc[s]] = v;
        }
        __syncthreads();
        #pragma unroll
        for (int ks = 0; ks < 4; ks++){
            wmma::fragment<wmma::matrix_a, 16,16,8, wmma::precision::tf32, wmma::row_major> af;
            wmma::load_matrix_sync(af, &sm.in.A[w*16][ks*8], LDA);
            #pragma unroll
            for (int i = 0; i < af.num_elements; i++) af.x[i] = wmma::__float_to_tf32(af.x[i]);
            #pragma unroll
            for (int n = 0; n < 4; n++){
                wmma::fragment<wmma::matrix_b, 16,16,8, wmma::precision::tf32, wmma::row_major> bf;
                wmma::load_matrix_sync(bf, &sm.in.B[ks*8][n*16], LDB);
                #pragma unroll
                for (int i = 0; i < bf.num_elements; i++) bf.x[i] = wmma::__float_to_tf32(bf.x[i]);
                wmma::mma_sync(acc[n], af, bf, acc[n]);
            }
        }
        __syncthreads();
    }

    // write C tile (reuses input smem)
    #pragma unroll
    for (int n = 0; n < 4; n++)
        wmma::store_matrix_sync(&sm.C[w*16][n*16], acc[n], LDC, wmma::mem_row_major);
    __syncthreads();

    // epilogue: bias + relu + noise + column sumsq (same math as scalar fc1)
    int c4 = (tid & 15) * 4;     // constant per thread across its rows
    float4 bj = *(const float4*)(b1 + c4);
    float css[4] = {0.f,0.f,0.f,0.f};
    #pragma unroll
    for (int i = 0; i < 8; i++){
        int idx = tid + i*256;           // 0..2047 float4 slots (128 rows x 16 slots)
        int row = idx >> 4;
        int growe = rowbase + row;
        if (growe < Nn){
            float4 cc = *(const float4*)&sm.C[row][c4];
            float4 nz = *(const float4*)(noise + growe*HID + c4);
            float4 v;
            v.x = fmaf(1e-5f, nz.x, fmaxf(cc.x + bj.x, 0.f));
            v.y = fmaf(1e-5f, nz.y, fmaxf(cc.y + bj.y, 0.f));
            v.z = fmaf(1e-5f, nz.z, fmaxf(cc.z + bj.z, 0.f));
            v.w = fmaf(1e-5f, nz.w, fmaxf(cc.w + bj.w, 0.f));
            css[0] = fmaf(v.x, v.x, css[0]);
            css[1] = fmaf(v.y, v.y, css[1]);
            css[2] = fmaf(v.z, v.z, css[2]);
            css[3] = fmaf(v.w, v.w, css[3]);
            *(float4*)(g_U[0] + growe*HID + c4) = v;
        }
    }
    atomicAdd(&scol[c4  ], css[0]); atomicAdd(&scol[c4+1], css[1]);
    atomicAdd(&scol[c4+2], css[2]); atomicAdd(&scol[c4+3], css[3]);
    __syncthreads();
    if (tid < HID) atomicAdd(&g_ss[tid], scol[tid]);
}

// ---------------- SpMM: R = inv_{i-1} .* (A @ U1), one warp per dst row (FROZEN R8 body) ----------------
__global__ void k_spmm(int u1Idx, int rIdx, int iter){
    const float* __restrict__ U = g_U[u1Idx];
    float* __restrict__ R = g_U[rIdx];
    __shared__ float inv_s[64];
    int t = threadIdx.x;
    if (t < 64){
        float ss = g_ss[(iter-1)*64 + t];
        float iv = 1.f / fmaxf(sqrtf(ss), 1e-8f);
        inv_s[t] = iv;
        if (blockIdx.x == 0) g_inv[iter*64 + t] = iv;
    }
    __syncthreads();
    int w    = (blockIdx.x*blockDim.x + t) >> 5;
    int lane = t & 31;
    if (w >= Nn) return;
    int e   = g_rowptr[w];
    int end = g_rowptr[w+1];
    float a0 = 0.f, a1 = 0.f;
    for (; e + 3 < end; e += 4){
        ull p0 = g_edge[e];
        ull p1 = g_edge[e+1];
        ull p2 = g_edge[e+2];
        ull p3 = g_edge[e+3];
        int   s0 = (int)(p0 & 0xffffffffu); float w0 = __uint_as_float((unsigned int)(p0 >> 32));
        int   s1 = (int)(p1 & 0xffffffffu); float w1 = __uint_as_float((unsigned int)(p1 >> 32));
        int   s2 = (int)(p2 & 0xffffffffu); float w2 = __uint_as_float((unsigned int)(p2 >> 32));
        int   s3 = (int)(p3 & 0xffffffffu); float w3 = __uint_as_float((unsigned int)(p3 >> 32));
        float2 v0 = *(const float2*)(U + (s0 << 6) + (lane << 1));
        float2 v1 = *(const float2*)(U + (s1 << 6) + (lane << 1));
        float2 v2 = *(const float2*)(U + (s2 << 6) + (lane << 1));
        float2 v3 = *(const float2*)(U + (s3 << 6) + (lane << 1));
        a0 = fmaf(w0, v0.x, a0); a1 = fmaf(w0, v0.y, a1);
        a0 = fmaf(w1, v1.x, a0); a1 = fmaf(w1, v1.y, a1);
        a0 = fmaf(w2, v2.x, a0); a1 = fmaf(w2, v2.y, a1);
        a0 = fmaf(w3, v3.x, a0); a1 = fmaf(w3, v3.y, a1);
    }
    for (; e < end; e++){
        ull p0 = g_edge[e];
        int   s0 = (int)(p0 & 0xffffffffu);
        float w0 = __uint_as_float((unsigned int)(p0 >> 32));
        float2 v0 = *(const float2*)(U + (s0 << 6) + (lane << 1));
        a0 = fmaf(w0, v0.x, a0); a1 = fmaf(w0, v0.y, a1);
    }
    float2 o;
    o.x = a0 * inv_s[lane*2];
    o.y = a1 * inv_s[lane*2 + 1];
    *(float2*)(R + (w << 6) + (lane << 1)) = o;
}

// ---------------- fused Gram-Schmidt step: dots -> grid barrier -> subtract + sumsq (FROZEN R8) ----
// Grid MUST be GS_BLOCKS (all co-resident) for the barrier to be deadlock-free.
__global__ void __launch_bounds__(256, 4) k_gs(int rIdx, int u1Idx, int u2Idx, int iter, int hasU2){
    float4* __restrict__ R        = (float4*)g_U[rIdx];
    const float4* __restrict__ U1 = (const float4*)g_U[u1Idx];
    const float4* __restrict__ U2 = (const float4*)g_U[u2Idx];
    __shared__ float s[192];
    int t = threadIdx.x;
    int c4 = (t & 15) * 4;
    int tid = blockIdx.x*blockDim.x + t;
    int stride = gridDim.x*blockDim.x;

    // ---- phase 1: column dot products ----
    float4 d1 = make_float4(0,0,0,0), d2 = d1, d3 = d1;
    if (hasU2){
        for (int i = tid; i < Nn*16; i += stride){
            float4 r = R[i], u1 = U1[i], u2 = U2[i];
            d1.x = fmaf(r.x,  u1.x, d1.x); d1.y = fmaf(r.y,  u1.y, d1.y);
            d1.z = fmaf(r.z,  u1.z, d1.z); d1.w = fmaf(r.w,  u1.w, d1.w);
            d2.x = fmaf(r.x,  u2.x, d2.x); d2.y = fmaf(r.y,  u2.y, d2.y);
            d2.z = fmaf(r.z,  u2.z, d2.z); d2.w = fmaf(r.w,  u2.w, d2.w);
            d3.x = fmaf(u1.x, u2.x, d3.x); d3.y = fmaf(u1.y, u2.y, d3.y);
            d3.z = fmaf(u1.z, u2.z, d3.z); d3.w = fmaf(u1.w, u2.w, d3.w);
        }
    } else {
        for (int i = tid; i < Nn*16; i += stride){
            float4 r = R[i], u1 = U1[i];
            d1.x = fmaf(r.x,  u1.x, d1.x); d1.y = fmaf(r.y,  u1.y, d1.y);
            d1.z = fmaf(r.z,  u1.z, d1.z); d1.w = fmaf(r.w,  u1.w, d1.w);
        }
    }
    if (t < 192) s[t] = 0.f;
    __syncthreads();
    atomicAdd(&s[      c4  ], d1.x); atomicAdd(&s[      c4+1], d1.y);
    atomicAdd(&s[      c4+2], d1.z); atomicAdd(&s[      c4+3], d1.w);
    if (hasU2){
        atomicAdd(&s[ 64 + c4  ], d2.x); atomicAdd(&s[ 64 + c4+1], d2.y);
        atomicAdd(&s[ 64 + c4+2], d2.z); atomicAdd(&s[ 64 + c4+3], d2.w);
        atomicAdd(&s[128 + c4  ], d3.x); atomicAdd(&s[128 + c4+1], d3.y);
        atomicAdd(&s[128 + c4+2], d3.z); atomicAdd(&s[128 + c4+3], d3.w);
    }
    __syncthreads();
    int nd = hasU2 ? 192 : 64;
    if (t < nd){
        atomicAdd(&g_dots[iter*192 + t], s[t]);
        __threadfence();        // release: dots visible before counter bump
    }
    __syncthreads();

    // ---- grid barrier ----
    if (t == 0){
        atomicAdd(&g_sync[iter], 1u);
        volatile unsigned* sy = (volatile unsigned*)&g_sync[iter];
        while (*sy < (unsigned)gridDim.x) __nanosleep(64);
        __threadfence();        // acquire
    }
    __syncthreads();

    // ---- phase 2: coefficients (MGS-exact), subtract, sumsq ----
    __shared__ float c1s[64], c2s[64], sss[64];
    if (t < 64){
        double inv1 = (double)g_inv[iter*64 + t];       // inv_{i-1}
        double inv2 = (double)g_inv[(iter-1)*64 + t];   // inv_{i-2} (slot 0 zeros at i==1)
        double d1v  = (double)__ldcg(&g_dots[iter*192 + t]);
        double d2v  = (double)__ldcg(&g_dots[iter*192 + 64 + t]);
        double d12  = (double)__ldcg(&g_dots[iter*192 + 128 + t]);
        double c1   = d1v*inv1*inv1;
        c1s[t] = (float)c1;                              // coeff on U1
        c2s[t] = (float)(inv2*inv2*(d2v - c1*d12));      // coeff on U2
        sss[t] = 0.f;
    }
    __syncthreads();
    float4 c1v = *(const float4*)&c1s[c4];
    float4 c2v = *(const float4*)&c2s[c4];
    float4 ss  = make_float4(0,0,0,0);
    if (hasU2){
        for (int i = tid; i < Nn*16; i += stride){
            float4 r = R[i], u1 = U1[i], u2 = U2[i];
            float4 w;
            w.x = r.x - c1v.x*u1.x - c2v.x*u2.x;
            w.y = r.y - c1v.y*u1.y - c2v.y*u2.y;
            w.z = r.z - c1v.z*u1.z - c2v.z*u2.z;
            w.w = r.w - c1v.w*u1.w - c2v.w*u2.w;
            ss.x = fmaf(w.x, w.x, ss.x); ss.y = fmaf(w.y, w.y, ss.y);
            ss.z = fmaf(w.z, w.z, ss.z); ss.w = fmaf(w.w, w.w, ss.w);
            R[i] = w;
        }
    } else {
        for (int i = tid; i < Nn*16; i += stride){
            float4 r = R[i], u1 = U1[i];
            float4 w;
            w.x = r.x - c1v.x*u1.x;
            w.y = r.y - c1v.y*u1.y;
            w.z = r.z - c1v.z*u1.z;
            w.w = r.w - c1v.w*u1.w;
            ss.x = fmaf(w.x, w.x, ss.x); ss.y = fmaf(w.y, w.y, ss.y);
            ss.z = fmaf(w.z, w.z, ss.z); ss.w = fmaf(w.w, w.w, ss.w);
            R[i] = w;
        }
    }
    atomicAdd(&sss[c4  ], ss.x); atomicAdd(&sss[c4+1], ss.y);
    atomicAdd(&sss[c4+2], ss.z); atomicAdd(&sss[c4+3], ss.w);
    __syncthreads();
    if (t < 64) atomicAdd(&g_ss[iter*64 + t], sss[t]);
}

// ---------------- final: out = (sum_i alpha_i*inv_i .* U_i) @ W2 + b2 ----------------
__global__ void __launch_bounds__(256) k_out(const float* __restrict__ W2, const float* __restrict__ b2,
                      const float* __restrict__ alpha, float* __restrict__ out){
    __shared__ float Ts[128][65];
    __shared__ float Bs[HID][CLS + 1];
    __shared__ float ck[KK+1][64];
    int tid = threadIdx.x;
    int rowbase = blockIdx.x * 128;
    if (tid < 64){
        #pragma unroll
        for (int i = 0; i < KK; i++)
            ck[i][tid] = alpha[tid*(KK+1) + i] * g_inv[(i+1)*64 + tid];
        float ssK  = g_ss[KK*64 + tid];
        float invK = 1.f / fmaxf(sqrtf(ssK), 1e-8f);
        ck[KK][tid] = alpha[tid*(KK+1) + KK] * invK;
    }
    for (int f = tid; f < HID*CLS; f += 256) Bs[f / CLS][f % CLS] = W2[f];
    __syncthreads();
    for (int f = tid; f < 128*64; f += 256){
        int r = f >> 6, col = f & 63;
        int grow = rowbase + r;
        float v = 0.f;
        if (grow < Nn){
            int idx = grow*64 + col;
            #pragma unroll
            for (int i = 0; i <= KK; i++)
                v = fmaf(ck[i][col], g_U[i][idx], v);
        }
        Ts[r][col] = v;
    }
    __syncthreads();
    int tr = tid & 31;   // rows tr*4..tr*4+3
    int tc = tid >> 5;   // cols tc*5..tc*5+4
    float acc[4][5];
    #pragma unroll
    for (int i = 0; i < 4; i++)
        #pragma unroll
        for (int j = 0; j < 5; j++) acc[i][j] = 0.f;
    for (int k = 0; k < 64; k++){
        float a[4], bb[5];
        #pragma unroll
        for (int i = 0; i < 4; i++) a[i] = Ts[tr*4 + i][k];
        #pragma unroll
        for (int j = 0; j < 5; j++) bb[j] = Bs[k][tc*5 + j];
        #pragma unroll
        for (int i = 0; i < 4; i++)
            #pragma unroll
            for (int j = 0; j < 5; j++)
                acc[i][j] = fmaf(a[i], bb[j], acc[i][j]);
    }
    #pragma unroll
    for (int i = 0; i < 4; i++){
        int row = rowbase + tr*4 + i;
        if (row < Nn){
            #pragma unroll
            for (int j = 0; j < 5; j++){
                int col = tc*5 + j;
                out[row*CLS + col] = acc[i][j] + b2[col];
            }
        }
    }
}

// ---------------- launch ----------------
extern "C" void kernel_launch(void* const* d_in, const int* in_sizes, int n_in,
                              void* d_out, int out_size){
    (void)in_sizes; (void)n_in; (void)out_size;
    const float* feat  = (const float*)d_in[0];
    const float* noise = (const float*)d_in[1];
    const float* normA = (const float*)d_in[2];
    const float* W1    = (const float*)d_in[3];
    const float* b1    = (const float*)d_in[4];
    const float* W2    = (const float*)d_in[5];
    const float* b2    = (const float*)d_in[6];
    const float* alpha = (const float*)d_in[7];
    const int*   ei    = (const int*)  d_in[8];
    const int* src = ei;
    const int* dst = ei + Ee;
    float* out = (float*)d_out;

    const int TB = 256;
    cudaStream_t ms = 0;               // capture/main stream
    cudaStream_t s2 = g_res.s2;

    // zeroing must precede both branches
    k_zero<<<(Nn + TB - 1)/TB, TB, 0, ms>>>();
    cudaEventRecord(g_res.evFork, ms);
    cudaStreamWaitEvent(s2, g_res.evFork, 0);

    // --- branch A (s2): CSR build ---
    k_count     <<<(Ee + TB - 1)/TB, TB, 0, s2>>>(dst);
    k_scan_fused<<<SCAN_BLOCKS, 1024, 0, s2>>>();
    k_scatter   <<<(Ee + TB - 1)/TB, TB, 0, s2>>>(src, dst, normA);
    cudaEventRecord(g_res.evJoin, s2);

    // --- branch B (main): fc1 (tf32 wmma v2) ---
    k_fc1<<<(Nn + FBM - 1)/FBM, 256, 0, ms>>>(feat, W1, b1, noise);

    // join
    cudaStreamWaitEvent(ms, g_res.evJoin, 0);

    for (int i = 1; i <= KK; i++){
        int hasU2 = (i >= 2) ? 1 : 0;
        int u2 = (i >= 2) ? (i - 2) : 0;      // unused when hasU2=0
        k_spmm<<<(Nn*32 + TB - 1)/TB, TB, 0, ms>>>(i - 1, i, i);
        k_gs  <<<GS_BLOCKS, TB, 0, ms>>>(i, i - 1, u2, i, hasU2);
    }

    k_out<<<(Nn + 127)/128, 256, 0, ms>>>(W2, b2, alpha, out);
}